// round 13
// baseline (speedup 1.0000x reference)
#include <cuda_runtime.h>
#include <cuda_fp16.h>
#include <cstdint>
#include <cstddef>

#define BATCH 32
#define NQ    1024
#define LSEQ  512
#define DIM   768
#define HB    16   // half-batch

// Scratch (device globals) — GEMM operands fp16
__device__ __half g_rq  [(size_t)BATCH * NQ   * DIM ];
__device__ __half g_rk  [(size_t)BATCH * LSEQ * DIM ];
__device__ __half g_rv  [(size_t)BATCH * LSEQ * DIM ];
__device__ __half g_rwv [DIM * DIM];
__device__ __half g_rwqt[DIM * DIM];
__device__ __half g_rwkt[DIM * DIM];
__device__ __half g_gt2 [DIM * DIM];                     // gt2[c][c'] = sum_d qw[d,c]kw[d,c']
__device__ float  g_w2  [DIM];
__device__ float  g_s2  [(size_t)BATCH * LSEQ];
__device__ __half g_kg  [(size_t)BATCH * LSEQ * DIM ];   // kG[b][l][c]
__device__ __half g_vpt [(size_t)BATCH * DIM  * LSEQ];   // vpT[b][d][l]
__device__ float  g_s   [(size_t)BATCH * NQ   * LSEQ];   // raw scores (fp32)
__device__ __half g_p   [(size_t)BATCH * NQ   * LSEQ];   // softmax probs (fp16)

__device__ __forceinline__ void mma_f16(float c[4],
    unsigned a0, unsigned a1, unsigned a2, unsigned a3,
    unsigned b0, unsigned b1)
{
    asm("mma.sync.aligned.m16n8k16.row.col.f32.f16.f16.f32 "
        "{%0,%1,%2,%3},{%4,%5,%6,%7},{%8,%9},{%0,%1,%2,%3};"
        : "+f"(c[0]), "+f"(c[1]), "+f"(c[2]), "+f"(c[3])
        : "r"(a0), "r"(a1), "r"(a2), "r"(a3), "r"(b0), "r"(b1));
}

__device__ __forceinline__ void ldsm_x4(unsigned r[4], uint32_t addr) {
    asm volatile("ldmatrix.sync.aligned.m8n8.x4.shared.b16 {%0,%1,%2,%3}, [%4];"
        : "=r"(r[0]), "=r"(r[1]), "=r"(r[2]), "=r"(r[3]) : "r"(addr));
}

__device__ __forceinline__ void cp16(uint32_t dst, const void* src) {
    asm volatile("cp.async.cg.shared.global [%0], [%1], 16;" :: "r"(dst), "l"(src));
}
#define CP_COMMIT() asm volatile("cp.async.commit_group;" ::: "memory")
#define CP_WAIT1()  asm volatile("cp.async.wait_group 1;" ::: "memory")
#define CP_WAIT0()  asm volatile("cp.async.wait_group 0;" ::: "memory")

__device__ __forceinline__ uint32_t s2u(const void* p) {
    uint32_t a;
    asm("{ .reg .u64 t; cvta.to.shared.u64 t, %1; cvt.u32.u64 %0, t; }"
        : "=r"(a) : "l"(p));
    return a;
}

__device__ __forceinline__ unsigned h2u(__half2 h) {
    return *(unsigned*)&h;
}

// ---------------------------------------------------------------------------
// 3-segment fp32 -> fp16 rounding (rn)
// ---------------------------------------------------------------------------
__global__ __launch_bounds__(256) void round3_h(
    const float* __restrict__ s0, __half* __restrict__ d0,
    const float* __restrict__ s1, __half* __restrict__ d1,
    const float* __restrict__ s2, __half* __restrict__ d2,
    int a4, int b4)
{
    int i = blockIdx.x * 256 + threadIdx.x;
    const float* src; __half* dst; int j;
    if (i < a4)            { src = s0; dst = d0; j = i; }
    else if (i < a4 + b4)  { src = s1; dst = d1; j = i - a4; }
    else                   { src = s2; dst = d2; j = i - a4 - b4; }
    float4 v = ((const float4*)src)[j];
    uint2 u;
    u.x = h2u(__floats2half2_rn(v.x, v.y));
    u.y = h2u(__floats2half2_rn(v.z, v.w));
    ((uint2*)dst)[j] = u;
}

// ---------------------------------------------------------------------------
// z=0: q_w -> rwqt transposed+rounded; z=1: k_w -> rwkt; z=2: v_w -> rwv copy.
// ---------------------------------------------------------------------------
__global__ __launch_bounds__(256) void transpose_round(
    const float* __restrict__ qw, __half* __restrict__ dqt,
    const float* __restrict__ kw, __half* __restrict__ dkt,
    const float* __restrict__ vw, __half* __restrict__ dv)
{
    const int tx = threadIdx.x, ty = threadIdx.y;
    const int x = blockIdx.x * 32 + tx;
    const int y = blockIdx.y * 32 + ty;

    if (blockIdx.z == 2) {
        #pragma unroll
        for (int i = 0; i < 32; i += 8)
            dv[(size_t)(y + i) * DIM + x] = __float2half_rn(vw[(size_t)(y + i) * DIM + x]);
        return;
    }

    __shared__ float tile[32][33];
    const float* src = blockIdx.z ? kw : qw;
    __half*      dst = blockIdx.z ? dkt : dqt;
    #pragma unroll
    for (int i = 0; i < 32; i += 8)
        tile[ty + i][tx] = src[(size_t)(y + i) * DIM + x];
    __syncthreads();
    const int xo = blockIdx.y * 32 + tx;
    const int yo = blockIdx.x * 32 + ty;
    #pragma unroll
    for (int i = 0; i < 32; i += 8)
        dst[(size_t)(yo + i) * DIM + xo] = __float2half_rn(tile[tx][ty + i]);
}

// ---------------------------------------------------------------------------
__global__ __launch_bounds__(256) void compute_w2(
    const float* __restrict__ kw, const float* __restrict__ bq,
    float* __restrict__ w2)
{
    __shared__ float part[8][32];
    const int cl = threadIdx.x & 31;
    const int dg = threadIdx.x >> 5;
    const int c  = blockIdx.x * 32 + cl;
    float acc = 0.f;
    const int d0 = dg * 96;
    #pragma unroll 8
    for (int d = d0; d < d0 + 96; d++)
        acc += __ldg(bq + d) * __ldg(kw + (size_t)d * DIM + c);
    part[dg][cl] = acc;
    __syncthreads();
    if (dg == 0) {
        float s = 0.f;
        #pragma unroll
        for (int i = 0; i < 8; i++) s += part[i][cl];
        w2[c] = s;
    }
}

// ---------------------------------------------------------------------------
// s2[row] = rk[row,:] . w2   (rk fp16, w2 fp32), one warp per row
// ---------------------------------------------------------------------------
__global__ __launch_bounds__(256) void compute_s2(
    const __half* __restrict__ rk, const float* __restrict__ w2,
    float* __restrict__ s2)
{
    const int row  = blockIdx.x * 8 + (threadIdx.x >> 5);
    const int lane = threadIdx.x & 31;
    const uint4*  kr = (const uint4*)(rk + (size_t)row * DIM);
    const float4* w4 = (const float4*)w2;
    float acc = 0.f;
    #pragma unroll
    for (int i = 0; i < 3; i++) {
        const int c = lane + 32 * i;
        uint4 u = kr[c];
        float4 wa = __ldg(w4 + 2 * c), wb = __ldg(w4 + 2 * c + 1);
        float2 f;
        f = __half22float2(*(__half2*)&u.x); acc += f.x * wa.x + f.y * wa.y;
        f = __half22float2(*(__half2*)&u.y); acc += f.x * wa.z + f.y * wa.w;
        f = __half22float2(*(__half2*)&u.z); acc += f.x * wb.x + f.y * wb.y;
        f = __half22float2(*(__half2*)&u.w); acc += f.x * wb.z + f.y * wb.w;
    }
    #pragma unroll
    for (int o = 16; o > 0; o >>= 1)
        acc += __shfl_xor_sync(0xffffffffu, acc, o);
    if (lane == 0) s2[row] = acc;
}

// ---------------------------------------------------------------------------
// C[M,N] = A[M,K] @ B[N,K]^T (+bias). fp16 in, fp32 accum.
// Block 128(M) x 256(N) x K64. 256 thr, warp grid 2x4, warp tile 64x64.
// A stage 16KB (128 rows x 128B), B stage 32KB (256 rows x 128B); 3 stages.
// 1 CTA/SM (launch_bounds(256,1)) -> ~190 regs, acc 128.
// biasMode: 0 none, 2 row bias[m]. halfOut: store fp16, else fp32.
// ---------------------------------------------------------------------------
#define A_TILE  16384
#define B_TILE  32768
#define STAGE   (A_TILE + B_TILE)       // 49152
#define SMEM_BYTES (3 * STAGE)          // 147456

__global__ __launch_bounds__(256, 1) void hgemm_nt(
    const __half* __restrict__ A, const __half* __restrict__ Bm,
    const float* __restrict__ bias, void* __restrict__ Cv,
    int K, int Ntot, long sA, long sB, long sC, int biasMode, int halfOut)
{
    extern __shared__ char smem[];
    const uint32_t sb = s2u(smem);

    const int tid  = threadIdx.x;
    const int lane = tid & 31;
    const int wid  = tid >> 5;
    const int wm   = (wid >> 2) * 64;    // 0,64
    const int wn   = (wid & 3) * 64;     // 0,64,128,192
    const int gid  = lane >> 2;
    const int tig  = lane & 3;

    const __half* Ab = A  + (size_t)blockIdx.z * sA + (size_t)blockIdx.y * 128 * K;
    const __half* Bb = Bm + (size_t)blockIdx.z * sB + (size_t)blockIdx.x * 256 * K;

    const int arow  = tid >> 1;          // 0..127
    const int abase = (tid & 1) * 4;     // chunk 0 or 4
    const int nkt   = K / 64;

    auto issue = [&](int t) {
        const int s = t % 3;
        const uint32_t As = sb + s * STAGE;
        const uint32_t Bs = As + A_TILE;
        // A: 2 threads per row, 4 chunks each
        {
            const __half* ga = Ab + (size_t)arow * K + t * 64;
            const uint32_t rowp = As + (uint32_t)arow * 128;
            const int r7 = arow & 7;
            #pragma unroll
            for (int i = 0; i < 4; i++) {
                const int ch = abase + i;
                cp16(rowp + (uint32_t)((ch ^ r7) * 16), ga + ch * 8);
            }
        }
        // B: 1 thread per row, 8 chunks each
        {
            const __half* gb = Bb + (size_t)tid * K + t * 64;
            const uint32_t rowp = Bs + (uint32_t)tid * 128;
            const int r7 = tid & 7;
            #pragma unroll
            for (int i = 0; i < 8; i++)
                cp16(rowp + (uint32_t)((i ^ r7) * 16), gb + i * 8);
        }
        CP_COMMIT();
    };

    issue(0); issue(1);

    float acc[4][8][4];
    #pragma unroll
    for (int mi = 0; mi < 4; mi++)
        #pragma unroll
        for (int nj = 0; nj < 8; nj++)
            #pragma unroll
            for (int r = 0; r < 4; r++) acc[mi][nj][r] = 0.f;

    const int la15 = lane & 15;
    const int lahi = lane >> 4;
    const int lbrow = ((lane >> 4) * 8) + (lane & 7);
    const int lbhi  = (lane >> 3) & 1;

    for (int t = 0; t < nkt; t++) {
        const uint32_t As = sb + (t % 3) * STAGE;
        const uint32_t Bs = As + A_TILE;

        CP_WAIT1();
        __syncthreads();
        if (t + 2 < nkt) issue(t + 2);

        #pragma unroll
        for (int kk = 0; kk < 4; kk++) {
            unsigned a[4][4], bq[4][4];
            #pragma unroll
            for (int mi = 0; mi < 4; mi++) {
                const int rowA = wm + mi * 16 + la15;
                const uint32_t addr = As + (uint32_t)rowA * 128
                    + (uint32_t)((((kk * 2) + lahi) ^ (rowA & 7)) * 16);
                ldsm_x4(a[mi], addr);
            }
            #pragma unroll
            for (int p = 0; p < 4; p++) {
                const int rowB = wn + p * 16 + lbrow;
                const uint32_t addr = Bs + (uint32_t)rowB * 128
                    + (uint32_t)((((kk * 2) + lbhi) ^ (rowB & 7)) * 16);
                ldsm_x4(bq[p], addr);
            }
            #pragma unroll
            for (int mi = 0; mi < 4; mi++)
                #pragma unroll
                for (int nj = 0; nj < 8; nj++)
                    mma_f16(acc[mi][nj], a[mi][0], a[mi][1], a[mi][2], a[mi][3],
                            bq[nj >> 1][(nj & 1) * 2], bq[nj >> 1][(nj & 1) * 2 + 1]);
        }
    }
    CP_WAIT0();

    // ---- epilogue ----
    #pragma unroll
    for (int mi = 0; mi < 4; mi++) {
        const int row0 = blockIdx.y * 128 + wm + mi * 16 + gid;
        float rb0 = (biasMode == 2) ? __ldg(bias + row0)     : 0.f;
        float rb1 = (biasMode == 2) ? __ldg(bias + row0 + 8) : 0.f;
        #pragma unroll
        for (int nj = 0; nj < 8; nj++) {
            const int col = blockIdx.x * 256 + wn + nj * 8 + 2 * tig;
            float c0 = acc[mi][nj][0] + rb0, c1 = acc[mi][nj][1] + rb0;
            float c2 = acc[mi][nj][2] + rb1, c3 = acc[mi][nj][3] + rb1;
            const size_t i0 = (size_t)(blockIdx.z * sC) + (size_t)row0 * Ntot + col;
            const size_t i1 = i0 + (size_t)8 * Ntot;
            if (halfOut) {
                __half* Ch = (__half*)Cv;
                *(__half2*)(Ch + i0) = __floats2half2_rn(c0, c1);
                *(__half2*)(Ch + i1) = __floats2half2_rn(c2, c3);
            } else {
                float* Cf = (float*)Cv;
                *(float2*)(Cf + i0) = make_float2(c0, c1);
                *(float2*)(Cf + i1) = make_float2(c2, c3);
            }
        }
    }
}

// ---------------------------------------------------------------------------
// softmax over rows of 512: fp32 scores + s2 bias -> fp16 probs.
// ---------------------------------------------------------------------------
__global__ __launch_bounds__(256) void softmax_rows(
    const float* __restrict__ S, const float* __restrict__ s2,
    __half* __restrict__ P, float scale)
{
    const int row  = blockIdx.x * 8 + (threadIdx.x >> 5);
    const int lane = threadIdx.x & 31;
    const int b    = row >> 10;
    const float4* r4 = (const float4*)(S + (size_t)row * LSEQ) + lane;
    const float4* b4 = (const float4*)(s2 + (size_t)b * LSEQ) + lane;

    float4 v[4];
    #pragma unroll
    for (int i = 0; i < 4; i++) {
        v[i] = r4[32 * i];
        float4 w = __ldg(b4 + 32 * i);
        v[i].x = (v[i].x + w.x) * scale; v[i].y = (v[i].y + w.y) * scale;
        v[i].z = (v[i].z + w.z) * scale; v[i].w = (v[i].w + w.w) * scale;
    }
    float mx = -3.4e38f;
    #pragma unroll
    for (int i = 0; i < 4; i++)
        mx = fmaxf(mx, fmaxf(fmaxf(v[i].x, v[i].y), fmaxf(v[i].z, v[i].w)));
    #pragma unroll
    for (int o = 16; o > 0; o >>= 1)
        mx = fmaxf(mx, __shfl_xor_sync(0xffffffffu, mx, o));
    float sum = 0.f;
    #pragma unroll
    for (int i = 0; i < 4; i++) {
        v[i].x = __expf(v[i].x - mx); v[i].y = __expf(v[i].y - mx);
        v[i].z = __expf(v[i].z - mx); v[i].w = __expf(v[i].w - mx);
        sum += v[i].x + v[i].y + v[i].z + v[i].w;
    }
    #pragma unroll
    for (int o = 16; o > 0; o >>= 1)
        sum += __shfl_xor_sync(0xffffffffu, sum, o);
    const float inv = 1.0f / sum;
    uint2* p8 = (uint2*)(P + (size_t)row * LSEQ) + lane;
    #pragma unroll
    for (int i = 0; i < 4; i++) {
        uint2 u;
        u.x = h2u(__floats2half2_rn(v[i].x * inv, v[i].y * inv));
        u.y = h2u(__floats2half2_rn(v[i].z * inv, v[i].w * inv));
        p8[32 * i] = u;
    }
}

extern "C" void kernel_launch(void* const* d_in, const int* in_sizes, int n_in,
                              void* d_out, int out_size)
{
    const float* q   = (const float*)d_in[0];
    const float* k   = (const float*)d_in[1];
    const float* v   = (const float*)d_in[2];
    const float* q_w = (const float*)d_in[3];
    const float* q_b = (const float*)d_in[4];
    const float* k_w = (const float*)d_in[5];
    const float* v_w = (const float*)d_in[7];
    const float* v_b = (const float*)d_in[8];
    float* out = (float*)d_out;

    __half *rq, *rk, *rv, *rwv, *rwqt, *rwkt, *gt2, *kg, *vpt, *p;
    float *w2, *s2p, *s;
    cudaGetSymbolAddress((void**)&rq,   g_rq);
    cudaGetSymbolAddress((void**)&rk,   g_rk);
    cudaGetSymbolAddress((void**)&rv,   g_rv);
    cudaGetSymbolAddress((void**)&rwv,  g_rwv);
    cudaGetSymbolAddress((void**)&rwqt, g_rwqt);
    cudaGetSymbolAddress((void**)&rwkt, g_rwkt);
    cudaGetSymbolAddress((void**)&gt2,  g_gt2);
    cudaGetSymbolAddress((void**)&w2,   g_w2);
    cudaGetSymbolAddress((void**)&s2p,  g_s2);
    cudaGetSymbolAddress((void**)&kg,   g_kg);
    cudaGetSymbolAddress((void**)&vpt,  g_vpt);
    cudaGetSymbolAddress((void**)&s,    g_s);
    cudaGetSymbolAddress((void**)&p,    g_p);

    static cudaStream_t s1 = nullptr, s2 = nullptr, s3 = nullptr;
    static cudaEvent_t eFork, eRqk, eRv, eGt2, eS2, eVpt, eDone;
    if (!s1) {
        cudaStreamCreateWithFlags(&s1, cudaStreamNonBlocking);
        cudaStreamCreateWithFlags(&s2, cudaStreamNonBlocking);
        cudaStreamCreateWithFlags(&s3, cudaStreamNonBlocking);
        cudaEventCreateWithFlags(&eFork, cudaEventDisableTiming);
        cudaEventCreateWithFlags(&eRqk,  cudaEventDisableTiming);
        cudaEventCreateWithFlags(&eRv,   cudaEventDisableTiming);
        cudaEventCreateWithFlags(&eGt2,  cudaEventDisableTiming);
        cudaEventCreateWithFlags(&eS2,   cudaEventDisableTiming);
        cudaEventCreateWithFlags(&eVpt,  cudaEventDisableTiming);
        cudaEventCreateWithFlags(&eDone, cudaEventDisableTiming);
        cudaFuncSetAttribute(hgemm_nt, cudaFuncAttributeMaxDynamicSharedMemorySize, SMEM_BYTES);
    }

    const int nq4 = BATCH * NQ * DIM / 4;
    const int nk4 = BATCH * LSEQ * DIM / 4;
    const float SCALE = 0.03608439182435161f;

    const size_t oRQ  = (size_t)HB * NQ * DIM;
    const size_t oRK  = (size_t)HB * LSEQ * DIM;
    const size_t oKG  = (size_t)HB * LSEQ * DIM;
    const size_t oS   = (size_t)HB * NQ * LSEQ;
    const size_t oS2  = (size_t)HB * LSEQ;
    const size_t oVPT = (size_t)HB * DIM * LSEQ;
    const size_t oOUT = (size_t)HB * NQ * DIM;

    // ---- fork ----
    cudaEventRecord(eFork, 0);
    cudaStreamWaitEvent(s1, eFork, 0);
    cudaStreamWaitEvent(s2, eFork, 0);
    cudaStreamWaitEvent(s3, eFork, 0);

    // s0: round q + k
    round3_h<<<(nq4 + nk4) / 256, 256, 0, 0>>>(q, rq, k, rk, k, rk, nq4, nk4);
    cudaEventRecord(eRqk, 0);

    // s1: weight transpose/round -> gt2[c][c'] = sum_d qw[d,c] kw[d,c']
    transpose_round<<<dim3(24, 24, 3), dim3(32, 8), 0, s1>>>(q_w, rwqt, k_w, rwkt, v_w, rwv);
    hgemm_nt<<<dim3(DIM / 256, DIM / 128, 1), 256, SMEM_BYTES, s1>>>(
        rwqt, rwkt, nullptr, gt2, DIM, DIM, 0, 0, 0, 0, 1);
    cudaEventRecord(eGt2, s1);

    // s2: w2 -> round v -> (after rk) s2
    compute_w2<<<DIM / 32, 256, 0, s2>>>(k_w, q_b, w2);
    round3_h<<<nk4 / 256, 256, 0, s2>>>(v, rv, v, rv, v, rv, nk4, 0);
    cudaEventRecord(eRv, s2);
    cudaStreamWaitEvent(s2, eRqk, 0);
    compute_s2<<<(BATCH * LSEQ) / 8, 256, 0, s2>>>(rk, w2, s2p);
    cudaEventRecord(eS2, s2);

    // s1: vpt (needs rv)  per-batch M=768, N=512
    cudaStreamWaitEvent(s1, eRv, 0);
    hgemm_nt<<<dim3(LSEQ / 256, DIM / 128, BATCH), 256, SMEM_BYTES, s1>>>(
        rwv, rv, v_b, vpt, DIM, LSEQ,
        0, (long)LSEQ * DIM, (long)DIM * LSEQ, 2, 1);
    cudaEventRecord(eVpt, s1);

    // ---- batch halves: s0 -> b 0..15, s3 -> b 16..31 ----

    // kG halves: M=8192, N=768
    cudaStreamWaitEvent(0, eGt2, 0);
    hgemm_nt<<<dim3(DIM / 256, (HB * LSEQ) / 128, 1), 256, SMEM_BYTES, 0>>>(
        rk, gt2, nullptr, kg, DIM, DIM, 0, 0, 0, 0, 1);
    cudaStreamWaitEvent(s3, eGt2, 0);
    cudaStreamWaitEvent(s3, eRqk, 0);
    hgemm_nt<<<dim3(DIM / 256, (HB * LSEQ) / 128, 1), 256, SMEM_BYTES, s3>>>(
        rk + oRK, gt2, nullptr, kg + oKG, DIM, DIM, 0, 0, 0, 0, 1);

    // S halves: per-batch M=1024, N=512, K=768
    hgemm_nt<<<dim3(LSEQ / 256, NQ / 128, HB), 256, SMEM_BYTES, 0>>>(
        rq, kg, nullptr, s, DIM, LSEQ,
        (long)NQ * DIM, (long)LSEQ * DIM, (long)NQ * LSEQ, 0, 0);
    hgemm_nt<<<dim3(LSEQ / 256, NQ / 128, HB), 256, SMEM_BYTES, s3>>>(
        rq + oRQ, kg + oKG, nullptr, s + oS, DIM, LSEQ,
        (long)NQ * DIM, (long)LSEQ * DIM, (long)NQ * LSEQ, 0, 0);

    // softmax halves -> fp16 probs
    cudaStreamWaitEvent(0, eS2, 0);
    softmax_rows<<<(HB * NQ) / 8, 256, 0, 0>>>(s, s2p, p, SCALE);
    cudaStreamWaitEvent(s3, eS2, 0);
    softmax_rows<<<(HB * NQ) / 8, 256, 0, s3>>>(s + oS, s2p + oS2, p + oS, SCALE);

    // out halves: per-batch M=1024, N=768, K=512
    cudaStreamWaitEvent(0, eVpt, 0);
    hgemm_nt<<<dim3(DIM / 256, NQ / 128, HB), 256, SMEM_BYTES, 0>>>(
        p, vpt, nullptr, out, LSEQ, DIM,
        (long)NQ * LSEQ, (long)DIM * LSEQ, (long)NQ * DIM, 0, 0);
    cudaStreamWaitEvent(s3, eVpt, 0);
    hgemm_nt<<<dim3(DIM / 256, NQ / 128, HB), 256, SMEM_BYTES, s3>>>(
        p + oS, vpt + oVPT, nullptr, out + oOUT, LSEQ, DIM,
        (long)NQ * LSEQ, (long)DIM * LSEQ, (long)NQ * DIM, 0, 0);

    // ---- join ----
    cudaEventRecord(eDone, s3);
    cudaStreamWaitEvent(0, eDone, 0);
}

// round 14
// speedup vs baseline: 1.2170x; 1.2170x over previous
#include <cuda_runtime.h>
#include <cuda_fp16.h>
#include <cstdint>
#include <cstddef>

#define BATCH 32
#define NQ    1024
#define LSEQ  512
#define DIM   768
#define HB    16   // half-batch

// Scratch (device globals) — GEMM operands fp16
__device__ __half g_rq  [(size_t)BATCH * NQ   * DIM ];
__device__ __half g_rk  [(size_t)BATCH * LSEQ * DIM ];
__device__ __half g_rv  [(size_t)BATCH * LSEQ * DIM ];
__device__ __half g_rwv [DIM * DIM];
__device__ __half g_rwqt[DIM * DIM];
__device__ __half g_rwkt[DIM * DIM];
__device__ __half g_gt2 [DIM * DIM];                     // gt2[c][c'] = sum_d qw[d,c]kw[d,c']
__device__ float  g_w2  [DIM];
__device__ float  g_s2  [(size_t)BATCH * LSEQ];
__device__ __half g_kg  [(size_t)BATCH * LSEQ * DIM ];   // kG[b][l][c]
__device__ __half g_vpt [(size_t)BATCH * DIM  * LSEQ];   // vpT[b][d][l]
__device__ __half g_sh  [(size_t)BATCH * NQ   * LSEQ];   // raw scores (fp16)
__device__ __half g_p   [(size_t)BATCH * NQ   * LSEQ];   // softmax probs (fp16)

__device__ __forceinline__ void mma_f16(float c[4],
    unsigned a0, unsigned a1, unsigned a2, unsigned a3,
    unsigned b0, unsigned b1)
{
    asm("mma.sync.aligned.m16n8k16.row.col.f32.f16.f16.f32 "
        "{%0,%1,%2,%3},{%4,%5,%6,%7},{%8,%9},{%0,%1,%2,%3};"
        : "+f"(c[0]), "+f"(c[1]), "+f"(c[2]), "+f"(c[3])
        : "r"(a0), "r"(a1), "r"(a2), "r"(a3), "r"(b0), "r"(b1));
}

__device__ __forceinline__ void ldsm_x4(unsigned r[4], uint32_t addr) {
    asm volatile("ldmatrix.sync.aligned.m8n8.x4.shared.b16 {%0,%1,%2,%3}, [%4];"
        : "=r"(r[0]), "=r"(r[1]), "=r"(r[2]), "=r"(r[3]) : "r"(addr));
}

__device__ __forceinline__ void cp16(uint32_t dst, const void* src) {
    asm volatile("cp.async.cg.shared.global [%0], [%1], 16;" :: "r"(dst), "l"(src));
}
#define CP_COMMIT() asm volatile("cp.async.commit_group;" ::: "memory")
#define CP_WAIT1()  asm volatile("cp.async.wait_group 1;" ::: "memory")
#define CP_WAIT0()  asm volatile("cp.async.wait_group 0;" ::: "memory")

__device__ __forceinline__ uint32_t s2u(const void* p) {
    uint32_t a;
    asm("{ .reg .u64 t; cvta.to.shared.u64 t, %1; cvt.u32.u64 %0, t; }"
        : "=r"(a) : "l"(p));
    return a;
}

__device__ __forceinline__ unsigned h2u(__half2 h) {
    return *(unsigned*)&h;
}

// ---------------------------------------------------------------------------
// 3-segment fp32 -> fp16 rounding (rn)
// ---------------------------------------------------------------------------
__global__ __launch_bounds__(256) void round3_h(
    const float* __restrict__ s0, __half* __restrict__ d0,
    const float* __restrict__ s1, __half* __restrict__ d1,
    const float* __restrict__ s2, __half* __restrict__ d2,
    int a4, int b4)
{
    int i = blockIdx.x * 256 + threadIdx.x;
    const float* src; __half* dst; int j;
    if (i < a4)            { src = s0; dst = d0; j = i; }
    else if (i < a4 + b4)  { src = s1; dst = d1; j = i - a4; }
    else                   { src = s2; dst = d2; j = i - a4 - b4; }
    float4 v = ((const float4*)src)[j];
    uint2 u;
    u.x = h2u(__floats2half2_rn(v.x, v.y));
    u.y = h2u(__floats2half2_rn(v.z, v.w));
    ((uint2*)dst)[j] = u;
}

// ---------------------------------------------------------------------------
// z=0: q_w -> rwqt transposed+rounded; z=1: k_w -> rwkt; z=2: v_w -> rwv copy.
// ---------------------------------------------------------------------------
__global__ __launch_bounds__(256) void transpose_round(
    const float* __restrict__ qw, __half* __restrict__ dqt,
    const float* __restrict__ kw, __half* __restrict__ dkt,
    const float* __restrict__ vw, __half* __restrict__ dv)
{
    const int tx = threadIdx.x, ty = threadIdx.y;
    const int x = blockIdx.x * 32 + tx;
    const int y = blockIdx.y * 32 + ty;

    if (blockIdx.z == 2) {
        #pragma unroll
        for (int i = 0; i < 32; i += 8)
            dv[(size_t)(y + i) * DIM + x] = __float2half_rn(vw[(size_t)(y + i) * DIM + x]);
        return;
    }

    __shared__ float tile[32][33];
    const float* src = blockIdx.z ? kw : qw;
    __half*      dst = blockIdx.z ? dkt : dqt;
    #pragma unroll
    for (int i = 0; i < 32; i += 8)
        tile[ty + i][tx] = src[(size_t)(y + i) * DIM + x];
    __syncthreads();
    const int xo = blockIdx.y * 32 + tx;
    const int yo = blockIdx.x * 32 + ty;
    #pragma unroll
    for (int i = 0; i < 32; i += 8)
        dst[(size_t)(yo + i) * DIM + xo] = __float2half_rn(tile[tx][ty + i]);
}

// ---------------------------------------------------------------------------
__global__ __launch_bounds__(256) void compute_w2(
    const float* __restrict__ kw, const float* __restrict__ bq,
    float* __restrict__ w2)
{
    __shared__ float part[8][32];
    const int cl = threadIdx.x & 31;
    const int dg = threadIdx.x >> 5;
    const int c  = blockIdx.x * 32 + cl;
    float acc = 0.f;
    const int d0 = dg * 96;
    #pragma unroll 8
    for (int d = d0; d < d0 + 96; d++)
        acc += __ldg(bq + d) * __ldg(kw + (size_t)d * DIM + c);
    part[dg][cl] = acc;
    __syncthreads();
    if (dg == 0) {
        float s = 0.f;
        #pragma unroll
        for (int i = 0; i < 8; i++) s += part[i][cl];
        w2[c] = s;
    }
}

// ---------------------------------------------------------------------------
// s2[row] = rk[row,:] . w2   (rk fp16, w2 fp32), one warp per row
// ---------------------------------------------------------------------------
__global__ __launch_bounds__(256) void compute_s2(
    const __half* __restrict__ rk, const float* __restrict__ w2,
    float* __restrict__ s2)
{
    const int row  = blockIdx.x * 8 + (threadIdx.x >> 5);
    const int lane = threadIdx.x & 31;
    const uint4*  kr = (const uint4*)(rk + (size_t)row * DIM);
    const float4* w4 = (const float4*)w2;
    float acc = 0.f;
    #pragma unroll
    for (int i = 0; i < 3; i++) {
        const int c = lane + 32 * i;
        uint4 u = kr[c];
        float4 wa = __ldg(w4 + 2 * c), wb = __ldg(w4 + 2 * c + 1);
        float2 f;
        f = __half22float2(*(__half2*)&u.x); acc += f.x * wa.x + f.y * wa.y;
        f = __half22float2(*(__half2*)&u.y); acc += f.x * wa.z + f.y * wa.w;
        f = __half22float2(*(__half2*)&u.z); acc += f.x * wb.x + f.y * wb.y;
        f = __half22float2(*(__half2*)&u.w); acc += f.x * wb.z + f.y * wb.w;
    }
    #pragma unroll
    for (int o = 16; o > 0; o >>= 1)
        acc += __shfl_xor_sync(0xffffffffu, acc, o);
    if (lane == 0) s2[row] = acc;
}

// ---------------------------------------------------------------------------
// C[M,N] = A[M,K] @ B[N,K]^T (+bias). fp16 in, fp32 accum.
// Block 128x128x64, 256 thr, warp grid 2x4, warp tile 64x32. (R12 proven)
// biasMode: 0 none, 2 row bias[m]. halfOut: store fp16, else fp32.
// ---------------------------------------------------------------------------
#define TILE_B  16384
#define STAGE   (2 * TILE_B)
#define SMEM_BYTES (3 * STAGE)

__global__ __launch_bounds__(256, 2) void hgemm_nt(
    const __half* __restrict__ A, const __half* __restrict__ Bm,
    const float* __restrict__ bias, void* __restrict__ Cv,
    int K, int Ntot, long sA, long sB, long sC, int biasMode, int halfOut)
{
    extern __shared__ char smem[];
    const uint32_t sb = s2u(smem);

    const int tid  = threadIdx.x;
    const int lane = tid & 31;
    const int wid  = tid >> 5;
    const int wm   = (wid >> 2) * 64;
    const int wn   = (wid & 3) * 32;
    const int gid  = lane >> 2;
    const int tig  = lane & 3;

    const __half* Ab = A  + (size_t)blockIdx.z * sA + (size_t)blockIdx.y * 128 * K;
    const __half* Bb = Bm + (size_t)blockIdx.z * sB + (size_t)blockIdx.x * 128 * K;

    const int crow  = tid >> 1;
    const int cbase = (tid & 1) * 4;
    const int nkt   = K / 64;

    auto issue = [&](int t) {
        const int s = t % 3;
        const uint32_t As = sb + s * STAGE;
        const uint32_t Bs = As + TILE_B;
        const __half* ga = Ab + (size_t)crow * K + t * 64;
        const __half* gb = Bb + (size_t)crow * K + t * 64;
        const uint32_t arow = As + (uint32_t)crow * 128;
        const uint32_t brow = Bs + (uint32_t)crow * 128;
        const int r7 = crow & 7;
        #pragma unroll
        for (int i = 0; i < 4; i++) {
            const int ch = cbase + i;
            const uint32_t off = (uint32_t)((ch ^ r7) * 16);
            cp16(arow + off, ga + ch * 8);
            cp16(brow + off, gb + ch * 8);
        }
        CP_COMMIT();
    };

    issue(0); issue(1);

    float acc[4][4][4];
    #pragma unroll
    for (int mi = 0; mi < 4; mi++)
        #pragma unroll
        for (int nj = 0; nj < 4; nj++)
            #pragma unroll
            for (int r = 0; r < 4; r++) acc[mi][nj][r] = 0.f;

    const int la15 = lane & 15;
    const int lahi = lane >> 4;
    const int lbrow = ((lane >> 4) * 8) + (lane & 7);
    const int lbhi  = (lane >> 3) & 1;

    for (int t = 0; t < nkt; t++) {
        const uint32_t As = sb + (t % 3) * STAGE;
        const uint32_t Bs = As + TILE_B;

        CP_WAIT1();
        __syncthreads();
        if (t + 2 < nkt) issue(t + 2);

        #pragma unroll
        for (int kk = 0; kk < 4; kk++) {
            unsigned a[4][4], bq[2][4];
            #pragma unroll
            for (int mi = 0; mi < 4; mi++) {
                const int rowA = wm + mi * 16 + la15;
                const uint32_t addr = As + (uint32_t)rowA * 128
                    + (uint32_t)((((kk * 2) + lahi) ^ (rowA & 7)) * 16);
                ldsm_x4(a[mi], addr);
            }
            #pragma unroll
            for (int p = 0; p < 2; p++) {
                const int rowB = wn + p * 16 + lbrow;
                const uint32_t addr = Bs + (uint32_t)rowB * 128
                    + (uint32_t)((((kk * 2) + lbhi) ^ (rowB & 7)) * 16);
                ldsm_x4(bq[p], addr);
            }
            #pragma unroll
            for (int mi = 0; mi < 4; mi++)
                #pragma unroll
                for (int nj = 0; nj < 4; nj++)
                    mma_f16(acc[mi][nj], a[mi][0], a[mi][1], a[mi][2], a[mi][3],
                            bq[nj >> 1][(nj & 1) * 2], bq[nj >> 1][(nj & 1) * 2 + 1]);
        }
    }
    CP_WAIT0();

    #pragma unroll
    for (int mi = 0; mi < 4; mi++) {
        const int row0 = blockIdx.y * 128 + wm + mi * 16 + gid;
        float rb0 = (biasMode == 2) ? __ldg(bias + row0)     : 0.f;
        float rb1 = (biasMode == 2) ? __ldg(bias + row0 + 8) : 0.f;
        #pragma unroll
        for (int nj = 0; nj < 4; nj++) {
            const int col = blockIdx.x * 128 + wn + nj * 8 + 2 * tig;
            float c0 = acc[mi][nj][0] + rb0, c1 = acc[mi][nj][1] + rb0;
            float c2 = acc[mi][nj][2] + rb1, c3 = acc[mi][nj][3] + rb1;
            const size_t i0 = (size_t)(blockIdx.z * sC) + (size_t)row0 * Ntot + col;
            const size_t i1 = i0 + (size_t)8 * Ntot;
            if (halfOut) {
                __half* Ch = (__half*)Cv;
                *(__half2*)(Ch + i0) = __floats2half2_rn(c0, c1);
                *(__half2*)(Ch + i1) = __floats2half2_rn(c2, c3);
            } else {
                float* Cf = (float*)Cv;
                *(float2*)(Cf + i0) = make_float2(c0, c1);
                *(float2*)(Cf + i1) = make_float2(c2, c3);
            }
        }
    }
}

// ---------------------------------------------------------------------------
// softmax over rows of 512: fp16 scores + fp32 s2 bias -> fp16 probs.
// ---------------------------------------------------------------------------
__global__ __launch_bounds__(256) void softmax_rows_h(
    const __half* __restrict__ Sh, const float* __restrict__ s2,
    __half* __restrict__ P, float scale)
{
    const int row  = blockIdx.x * 8 + (threadIdx.x >> 5);
    const int lane = threadIdx.x & 31;
    const int b    = row >> 10;
    const uint2*  r8 = (const uint2*)(Sh + (size_t)row * LSEQ) + lane;   // 4 halves per uint2
    const float4* b4 = (const float4*)(s2 + (size_t)b * LSEQ) + lane;

    float4 v[4];
    #pragma unroll
    for (int i = 0; i < 4; i++) {
        uint2 u = r8[32 * i];
        float2 lo = __half22float2(*(__half2*)&u.x);
        float2 hi = __half22float2(*(__half2*)&u.y);
        float4 w = __ldg(b4 + 32 * i);
        v[i].x = (lo.x + w.x) * scale; v[i].y = (lo.y + w.y) * scale;
        v[i].z = (hi.x + w.z) * scale; v[i].w = (hi.y + w.w) * scale;
    }
    float mx = -3.4e38f;
    #pragma unroll
    for (int i = 0; i < 4; i++)
        mx = fmaxf(mx, fmaxf(fmaxf(v[i].x, v[i].y), fmaxf(v[i].z, v[i].w)));
    #pragma unroll
    for (int o = 16; o > 0; o >>= 1)
        mx = fmaxf(mx, __shfl_xor_sync(0xffffffffu, mx, o));
    float sum = 0.f;
    #pragma unroll
    for (int i = 0; i < 4; i++) {
        v[i].x = __expf(v[i].x - mx); v[i].y = __expf(v[i].y - mx);
        v[i].z = __expf(v[i].z - mx); v[i].w = __expf(v[i].w - mx);
        sum += v[i].x + v[i].y + v[i].z + v[i].w;
    }
    #pragma unroll
    for (int o = 16; o > 0; o >>= 1)
        sum += __shfl_xor_sync(0xffffffffu, sum, o);
    const float inv = 1.0f / sum;
    uint2* p8 = (uint2*)(P + (size_t)row * LSEQ) + lane;
    #pragma unroll
    for (int i = 0; i < 4; i++) {
        uint2 u;
        u.x = h2u(__floats2half2_rn(v[i].x * inv, v[i].y * inv));
        u.y = h2u(__floats2half2_rn(v[i].z * inv, v[i].w * inv));
        p8[32 * i] = u;
    }
}

extern "C" void kernel_launch(void* const* d_in, const int* in_sizes, int n_in,
                              void* d_out, int out_size)
{
    const float* q   = (const float*)d_in[0];
    const float* k   = (const float*)d_in[1];
    const float* v   = (const float*)d_in[2];
    const float* q_w = (const float*)d_in[3];
    const float* q_b = (const float*)d_in[4];
    const float* k_w = (const float*)d_in[5];
    const float* v_w = (const float*)d_in[7];
    const float* v_b = (const float*)d_in[8];
    float* out = (float*)d_out;

    __half *rq, *rk, *rv, *rwv, *rwqt, *rwkt, *gt2, *kg, *vpt, *sh, *p;
    float *w2, *s2p;
    cudaGetSymbolAddress((void**)&rq,   g_rq);
    cudaGetSymbolAddress((void**)&rk,   g_rk);
    cudaGetSymbolAddress((void**)&rv,   g_rv);
    cudaGetSymbolAddress((void**)&rwv,  g_rwv);
    cudaGetSymbolAddress((void**)&rwqt, g_rwqt);
    cudaGetSymbolAddress((void**)&rwkt, g_rwkt);
    cudaGetSymbolAddress((void**)&gt2,  g_gt2);
    cudaGetSymbolAddress((void**)&w2,   g_w2);
    cudaGetSymbolAddress((void**)&s2p,  g_s2);
    cudaGetSymbolAddress((void**)&kg,   g_kg);
    cudaGetSymbolAddress((void**)&vpt,  g_vpt);
    cudaGetSymbolAddress((void**)&sh,   g_sh);
    cudaGetSymbolAddress((void**)&p,    g_p);

    static cudaStream_t s1 = nullptr, s2 = nullptr, s3 = nullptr;
    static cudaEvent_t eFork, eRqk, eRv, eGt2, eS2, eVpt, eDone;
    if (!s1) {
        cudaStreamCreateWithFlags(&s1, cudaStreamNonBlocking);
        cudaStreamCreateWithFlags(&s2, cudaStreamNonBlocking);
        cudaStreamCreateWithFlags(&s3, cudaStreamNonBlocking);
        cudaEventCreateWithFlags(&eFork, cudaEventDisableTiming);
        cudaEventCreateWithFlags(&eRqk,  cudaEventDisableTiming);
        cudaEventCreateWithFlags(&eRv,   cudaEventDisableTiming);
        cudaEventCreateWithFlags(&eGt2,  cudaEventDisableTiming);
        cudaEventCreateWithFlags(&eS2,   cudaEventDisableTiming);
        cudaEventCreateWithFlags(&eVpt,  cudaEventDisableTiming);
        cudaEventCreateWithFlags(&eDone, cudaEventDisableTiming);
        cudaFuncSetAttribute(hgemm_nt, cudaFuncAttributeMaxDynamicSharedMemorySize, SMEM_BYTES);
    }

    const int nq4 = BATCH * NQ * DIM / 4;
    const int nk4 = BATCH * LSEQ * DIM / 4;
    const float SCALE = 0.03608439182435161f;

    const size_t oRQ  = (size_t)HB * NQ * DIM;
    const size_t oRK  = (size_t)HB * LSEQ * DIM;
    const size_t oKG  = (size_t)HB * LSEQ * DIM;
    const size_t oS   = (size_t)HB * NQ * LSEQ;
    const size_t oS2  = (size_t)HB * LSEQ;
    const size_t oVPT = (size_t)HB * DIM * LSEQ;
    const size_t oOUT = (size_t)HB * NQ * DIM;

    // ---- fork ----
    cudaEventRecord(eFork, 0);
    cudaStreamWaitEvent(s1, eFork, 0);
    cudaStreamWaitEvent(s2, eFork, 0);
    cudaStreamWaitEvent(s3, eFork, 0);

    // s0: round q + k
    round3_h<<<(nq4 + nk4) / 256, 256, 0, 0>>>(q, rq, k, rk, k, rk, nq4, nk4);
    cudaEventRecord(eRqk, 0);

    // s1: weight transpose/round -> gt2[c][c'] = sum_d qw[d,c] kw[d,c']
    transpose_round<<<dim3(24, 24, 3), dim3(32, 8), 0, s1>>>(q_w, rwqt, k_w, rwkt, v_w, rwv);
    hgemm_nt<<<dim3(DIM / 128, DIM / 128, 1), 256, SMEM_BYTES, s1>>>(
        rwqt, rwkt, nullptr, gt2, DIM, DIM, 0, 0, 0, 0, 1);
    cudaEventRecord(eGt2, s1);

    // s2: w2 -> round v -> (after rk) s2
    compute_w2<<<DIM / 32, 256, 0, s2>>>(k_w, q_b, w2);
    round3_h<<<nk4 / 256, 256, 0, s2>>>(v, rv, v, rv, v, rv, nk4, 0);
    cudaEventRecord(eRv, s2);
    cudaStreamWaitEvent(s2, eRqk, 0);
    compute_s2<<<(BATCH * LSEQ) / 8, 256, 0, s2>>>(rk, w2, s2p);
    cudaEventRecord(eS2, s2);

    // s1: vpt (needs rv)  per-batch M=768, N=512
    cudaStreamWaitEvent(s1, eRv, 0);
    hgemm_nt<<<dim3(LSEQ / 128, DIM / 128, BATCH), 256, SMEM_BYTES, s1>>>(
        rwv, rv, v_b, vpt, DIM, LSEQ,
        0, (long)LSEQ * DIM, (long)DIM * LSEQ, 2, 1);
    cudaEventRecord(eVpt, s1);

    // ---- batch halves: s0 -> b 0..15, s3 -> b 16..31 ----

    // kG halves: M=8192, N=768
    cudaStreamWaitEvent(0, eGt2, 0);
    hgemm_nt<<<dim3(DIM / 128, (HB * LSEQ) / 128, 1), 256, SMEM_BYTES, 0>>>(
        rk, gt2, nullptr, kg, DIM, DIM, 0, 0, 0, 0, 1);
    cudaStreamWaitEvent(s3, eGt2, 0);
    cudaStreamWaitEvent(s3, eRqk, 0);
    hgemm_nt<<<dim3(DIM / 128, (HB * LSEQ) / 128, 1), 256, SMEM_BYTES, s3>>>(
        rk + oRK, gt2, nullptr, kg + oKG, DIM, DIM, 0, 0, 0, 0, 1);

    // S halves: per-batch M=1024, N=512, K=768 -> fp16 scores
    hgemm_nt<<<dim3(LSEQ / 128, NQ / 128, HB), 256, SMEM_BYTES, 0>>>(
        rq, kg, nullptr, sh, DIM, LSEQ,
        (long)NQ * DIM, (long)LSEQ * DIM, (long)NQ * LSEQ, 0, 1);
    hgemm_nt<<<dim3(LSEQ / 128, NQ / 128, HB), 256, SMEM_BYTES, s3>>>(
        rq + oRQ, kg + oKG, nullptr, sh + oS, DIM, LSEQ,
        (long)NQ * DIM, (long)LSEQ * DIM, (long)NQ * LSEQ, 0, 1);

    // softmax halves (fp16 in) -> fp16 probs
    cudaStreamWaitEvent(0, eS2, 0);
    softmax_rows_h<<<(HB * NQ) / 8, 256, 0, 0>>>(sh, s2p, p, SCALE);
    cudaStreamWaitEvent(s3, eS2, 0);
    softmax_rows_h<<<(HB * NQ) / 8, 256, 0, s3>>>(sh + oS, s2p + oS2, p + oS, SCALE);

    // out halves: per-batch M=1024, N=768, K=512 -> fp32 to d_out
    cudaStreamWaitEvent(0, eVpt, 0);
    hgemm_nt<<<dim3(DIM / 128, NQ / 128, HB), 256, SMEM_BYTES, 0>>>(
        p, vpt, nullptr, out, LSEQ, DIM,
        (long)NQ * LSEQ, (long)DIM * LSEQ, (long)NQ * DIM, 0, 0);
    cudaStreamWaitEvent(s3, eVpt, 0);
    hgemm_nt<<<dim3(DIM / 128, NQ / 128, HB), 256, SMEM_BYTES, s3>>>(
        p + oS, vpt + oVPT, nullptr, out + oOUT, LSEQ, DIM,
        (long)NQ * LSEQ, (long)DIM * LSEQ, (long)NQ * DIM, 0, 0);

    // ---- join ----
    cudaEventRecord(eDone, s3);
    cudaStreamWaitEvent(0, eDone, 0);
}

// round 15
// speedup vs baseline: 1.2238x; 1.0056x over previous
#include <cuda_runtime.h>
#include <cuda_fp16.h>
#include <cstdint>
#include <cstddef>

#define BATCH 32
#define NQ    1024
#define LSEQ  512
#define DIM   768
#define HB    16   // half-batch

// Scratch (device globals) — GEMM operands fp16
__device__ __half g_rq  [(size_t)BATCH * NQ   * DIM ];
__device__ __half g_rk  [(size_t)BATCH * LSEQ * DIM ];
__device__ __half g_rv  [(size_t)BATCH * LSEQ * DIM ];
__device__ __half g_rwv [DIM * DIM];
__device__ __half g_rwqt[DIM * DIM];
__device__ __half g_rwkt[DIM * DIM];
__device__ float  g_gtp [4 * DIM * DIM];                 // gt2 split-K partials (fp32)
__device__ __half g_gt2 [DIM * DIM];                     // gt2[c][c'] = sum_d qw[d,c]kw[d,c']
__device__ float  g_w2  [DIM];
__device__ float  g_s2  [(size_t)BATCH * LSEQ];
__device__ __half g_kg  [(size_t)BATCH * LSEQ * DIM ];   // kG[b][l][c]
__device__ __half g_vpt [(size_t)BATCH * DIM  * LSEQ];   // vpT[b][d][l]
__device__ __half g_sh  [(size_t)BATCH * NQ   * LSEQ];   // raw scores (fp16)
__device__ __half g_p   [(size_t)BATCH * NQ   * LSEQ];   // softmax probs (fp16)

__device__ __forceinline__ void mma_f16(float c[4],
    unsigned a0, unsigned a1, unsigned a2, unsigned a3,
    unsigned b0, unsigned b1)
{
    asm("mma.sync.aligned.m16n8k16.row.col.f32.f16.f16.f32 "
        "{%0,%1,%2,%3},{%4,%5,%6,%7},{%8,%9},{%0,%1,%2,%3};"
        : "+f"(c[0]), "+f"(c[1]), "+f"(c[2]), "+f"(c[3])
        : "r"(a0), "r"(a1), "r"(a2), "r"(a3), "r"(b0), "r"(b1));
}

__device__ __forceinline__ void ldsm_x4(unsigned r[4], uint32_t addr) {
    asm volatile("ldmatrix.sync.aligned.m8n8.x4.shared.b16 {%0,%1,%2,%3}, [%4];"
        : "=r"(r[0]), "=r"(r[1]), "=r"(r[2]), "=r"(r[3]) : "r"(addr));
}

__device__ __forceinline__ void cp16(uint32_t dst, const void* src) {
    asm volatile("cp.async.cg.shared.global [%0], [%1], 16;" :: "r"(dst), "l"(src));
}
#define CP_COMMIT() asm volatile("cp.async.commit_group;" ::: "memory")
#define CP_WAIT1()  asm volatile("cp.async.wait_group 1;" ::: "memory")
#define CP_WAIT0()  asm volatile("cp.async.wait_group 0;" ::: "memory")

__device__ __forceinline__ uint32_t s2u(const void* p) {
    uint32_t a;
    asm("{ .reg .u64 t; cvta.to.shared.u64 t, %1; cvt.u32.u64 %0, t; }"
        : "=r"(a) : "l"(p));
    return a;
}

__device__ __forceinline__ unsigned h2u(__half2 h) {
    return *(unsigned*)&h;
}

// ---------------------------------------------------------------------------
// 3-segment fp32 -> fp16 rounding (rn)
// ---------------------------------------------------------------------------
__global__ __launch_bounds__(256) void round3_h(
    const float* __restrict__ s0, __half* __restrict__ d0,
    const float* __restrict__ s1, __half* __restrict__ d1,
    const float* __restrict__ s2, __half* __restrict__ d2,
    int a4, int b4)
{
    int i = blockIdx.x * 256 + threadIdx.x;
    const float* src; __half* dst; int j;
    if (i < a4)            { src = s0; dst = d0; j = i; }
    else if (i < a4 + b4)  { src = s1; dst = d1; j = i - a4; }
    else                   { src = s2; dst = d2; j = i - a4 - b4; }
    float4 v = ((const float4*)src)[j];
    uint2 u;
    u.x = h2u(__floats2half2_rn(v.x, v.y));
    u.y = h2u(__floats2half2_rn(v.z, v.w));
    ((uint2*)dst)[j] = u;
}

// ---------------------------------------------------------------------------
// z=0: q_w -> rwqt transposed+rounded; z=1: k_w -> rwkt; z=2: v_w -> rwv copy.
// ---------------------------------------------------------------------------
__global__ __launch_bounds__(256) void transpose_round(
    const float* __restrict__ qw, __half* __restrict__ dqt,
    const float* __restrict__ kw, __half* __restrict__ dkt,
    const float* __restrict__ vw, __half* __restrict__ dv)
{
    const int tx = threadIdx.x, ty = threadIdx.y;
    const int x = blockIdx.x * 32 + tx;
    const int y = blockIdx.y * 32 + ty;

    if (blockIdx.z == 2) {
        #pragma unroll
        for (int i = 0; i < 32; i += 8)
            dv[(size_t)(y + i) * DIM + x] = __float2half_rn(vw[(size_t)(y + i) * DIM + x]);
        return;
    }

    __shared__ float tile[32][33];
    const float* src = blockIdx.z ? kw : qw;
    __half*      dst = blockIdx.z ? dkt : dqt;
    #pragma unroll
    for (int i = 0; i < 32; i += 8)
        tile[ty + i][tx] = src[(size_t)(y + i) * DIM + x];
    __syncthreads();
    const int xo = blockIdx.y * 32 + tx;
    const int yo = blockIdx.x * 32 + ty;
    #pragma unroll
    for (int i = 0; i < 32; i += 8)
        dst[(size_t)(yo + i) * DIM + xo] = __float2half_rn(tile[tx][ty + i]);
}

// ---------------------------------------------------------------------------
// gt2 split-K reduce: dst[i] = fp16(p[i] + p[i+n] + p[i+2n] + p[i+3n])
// ---------------------------------------------------------------------------
__global__ __launch_bounds__(256) void reduce4_round(
    const float* __restrict__ p, __half* __restrict__ dst, int n4)
{
    int i = blockIdx.x * 256 + threadIdx.x;
    const float4* p4 = (const float4*)p;
    float4 a = p4[i], b = p4[i + n4], c = p4[i + 2 * n4], d = p4[i + 3 * n4];
    float4 s;
    s.x = (a.x + b.x) + (c.x + d.x);
    s.y = (a.y + b.y) + (c.y + d.y);
    s.z = (a.z + b.z) + (c.z + d.z);
    s.w = (a.w + b.w) + (c.w + d.w);
    uint2 u;
    u.x = h2u(__floats2half2_rn(s.x, s.y));
    u.y = h2u(__floats2half2_rn(s.z, s.w));
    ((uint2*)dst)[i] = u;
}

// ---------------------------------------------------------------------------
__global__ __launch_bounds__(256) void compute_w2(
    const float* __restrict__ kw, const float* __restrict__ bq,
    float* __restrict__ w2)
{
    __shared__ float part[8][32];
    const int cl = threadIdx.x & 31;
    const int dg = threadIdx.x >> 5;
    const int c  = blockIdx.x * 32 + cl;
    float acc = 0.f;
    const int d0 = dg * 96;
    #pragma unroll 8
    for (int d = d0; d < d0 + 96; d++)
        acc += __ldg(bq + d) * __ldg(kw + (size_t)d * DIM + c);
    part[dg][cl] = acc;
    __syncthreads();
    if (dg == 0) {
        float s = 0.f;
        #pragma unroll
        for (int i = 0; i < 8; i++) s += part[i][cl];
        w2[c] = s;
    }
}

// ---------------------------------------------------------------------------
// s2[row] = rk[row,:] . w2   (rk fp16, w2 fp32), one warp per row
// ---------------------------------------------------------------------------
__global__ __launch_bounds__(256) void compute_s2(
    const __half* __restrict__ rk, const float* __restrict__ w2,
    float* __restrict__ s2)
{
    const int row  = blockIdx.x * 8 + (threadIdx.x >> 5);
    const int lane = threadIdx.x & 31;
    const uint4*  kr = (const uint4*)(rk + (size_t)row * DIM);
    const float4* w4 = (const float4*)w2;
    float acc = 0.f;
    #pragma unroll
    for (int i = 0; i < 3; i++) {
        const int c = lane + 32 * i;
        uint4 u = kr[c];
        float4 wa = __ldg(w4 + 2 * c), wb = __ldg(w4 + 2 * c + 1);
        float2 f;
        f = __half22float2(*(__half2*)&u.x); acc += f.x * wa.x + f.y * wa.y;
        f = __half22float2(*(__half2*)&u.y); acc += f.x * wa.z + f.y * wa.w;
        f = __half22float2(*(__half2*)&u.z); acc += f.x * wb.x + f.y * wb.y;
        f = __half22float2(*(__half2*)&u.w); acc += f.x * wb.z + f.y * wb.w;
    }
    #pragma unroll
    for (int o = 16; o > 0; o >>= 1)
        acc += __shfl_xor_sync(0xffffffffu, acc, o);
    if (lane == 0) s2[row] = acc;
}

// ---------------------------------------------------------------------------
// C[M,N] = A[M,K] @ B[N,K]^T (+bias). fp16 in, fp32 accum.
// Block 128x128x64, 256 thr, warp grid 2x4, warp tile 64x32. (R12 proven)
// lda: row stride of A and B (elements); K: reduction length (<= lda usable).
// biasMode: 0 none, 2 row bias[m]. halfOut: store fp16, else fp32.
// ---------------------------------------------------------------------------
#define TILE_B  16384
#define STAGE   (2 * TILE_B)
#define SMEM_BYTES (3 * STAGE)

__global__ __launch_bounds__(256, 2) void hgemm_nt(
    const __half* __restrict__ A, const __half* __restrict__ Bm,
    const float* __restrict__ bias, void* __restrict__ Cv,
    int K, int lda, int Ntot, long sA, long sB, long sC, int biasMode, int halfOut)
{
    extern __shared__ char smem[];
    const uint32_t sb = s2u(smem);

    const int tid  = threadIdx.x;
    const int lane = tid & 31;
    const int wid  = tid >> 5;
    const int wm   = (wid >> 2) * 64;
    const int wn   = (wid & 3) * 32;
    const int gid  = lane >> 2;
    const int tig  = lane & 3;

    const __half* Ab = A  + (size_t)blockIdx.z * sA + (size_t)blockIdx.y * 128 * lda;
    const __half* Bb = Bm + (size_t)blockIdx.z * sB + (size_t)blockIdx.x * 128 * lda;

    const int crow  = tid >> 1;
    const int cbase = (tid & 1) * 4;
    const int nkt   = K / 64;

    auto issue = [&](int t) {
        const int s = t % 3;
        const uint32_t As = sb + s * STAGE;
        const uint32_t Bs = As + TILE_B;
        const __half* ga = Ab + (size_t)crow * lda + t * 64;
        const __half* gb = Bb + (size_t)crow * lda + t * 64;
        const uint32_t arow = As + (uint32_t)crow * 128;
        const uint32_t brow = Bs + (uint32_t)crow * 128;
        const int r7 = crow & 7;
        #pragma unroll
        for (int i = 0; i < 4; i++) {
            const int ch = cbase + i;
            const uint32_t off = (uint32_t)((ch ^ r7) * 16);
            cp16(arow + off, ga + ch * 8);
            cp16(brow + off, gb + ch * 8);
        }
        CP_COMMIT();
    };

    issue(0); issue(1);

    float acc[4][4][4];
    #pragma unroll
    for (int mi = 0; mi < 4; mi++)
        #pragma unroll
        for (int nj = 0; nj < 4; nj++)
            #pragma unroll
            for (int r = 0; r < 4; r++) acc[mi][nj][r] = 0.f;

    const int la15 = lane & 15;
    const int lahi = lane >> 4;
    const int lbrow = ((lane >> 4) * 8) + (lane & 7);
    const int lbhi  = (lane >> 3) & 1;

    for (int t = 0; t < nkt; t++) {
        const uint32_t As = sb + (t % 3) * STAGE;
        const uint32_t Bs = As + TILE_B;

        CP_WAIT1();
        __syncthreads();
        if (t + 2 < nkt) issue(t + 2);

        #pragma unroll
        for (int kk = 0; kk < 4; kk++) {
            unsigned a[4][4], bq[2][4];
            #pragma unroll
            for (int mi = 0; mi < 4; mi++) {
                const int rowA = wm + mi * 16 + la15;
                const uint32_t addr = As + (uint32_t)rowA * 128
                    + (uint32_t)((((kk * 2) + lahi) ^ (rowA & 7)) * 16);
                ldsm_x4(a[mi], addr);
            }
            #pragma unroll
            for (int p = 0; p < 2; p++) {
                const int rowB = wn + p * 16 + lbrow;
                const uint32_t addr = Bs + (uint32_t)rowB * 128
                    + (uint32_t)((((kk * 2) + lbhi) ^ (rowB & 7)) * 16);
                ldsm_x4(bq[p], addr);
            }
            #pragma unroll
            for (int mi = 0; mi < 4; mi++)
                #pragma unroll
                for (int nj = 0; nj < 4; nj++)
                    mma_f16(acc[mi][nj], a[mi][0], a[mi][1], a[mi][2], a[mi][3],
                            bq[nj >> 1][(nj & 1) * 2], bq[nj >> 1][(nj & 1) * 2 + 1]);
        }
    }
    CP_WAIT0();

    #pragma unroll
    for (int mi = 0; mi < 4; mi++) {
        const int row0 = blockIdx.y * 128 + wm + mi * 16 + gid;
        float rb0 = (biasMode == 2) ? __ldg(bias + row0)     : 0.f;
        float rb1 = (biasMode == 2) ? __ldg(bias + row0 + 8) : 0.f;
        #pragma unroll
        for (int nj = 0; nj < 4; nj++) {
            const int col = blockIdx.x * 128 + wn + nj * 8 + 2 * tig;
            float c0 = acc[mi][nj][0] + rb0, c1 = acc[mi][nj][1] + rb0;
            float c2 = acc[mi][nj][2] + rb1, c3 = acc[mi][nj][3] + rb1;
            const size_t i0 = (size_t)(blockIdx.z * sC) + (size_t)row0 * Ntot + col;
            const size_t i1 = i0 + (size_t)8 * Ntot;
            if (halfOut) {
                __half* Ch = (__half*)Cv;
                *(__half2*)(Ch + i0) = __floats2half2_rn(c0, c1);
                *(__half2*)(Ch + i1) = __floats2half2_rn(c2, c3);
            } else {
                float* Cf = (float*)Cv;
                *(float2*)(Cf + i0) = make_float2(c0, c1);
                *(float2*)(Cf + i1) = make_float2(c2, c3);
            }
        }
    }
}

// ---------------------------------------------------------------------------
// softmax over rows of 512: fp16 scores + fp32 s2 bias -> fp16 probs.
// ---------------------------------------------------------------------------
__global__ __launch_bounds__(256) void softmax_rows_h(
    const __half* __restrict__ Sh, const float* __restrict__ s2,
    __half* __restrict__ P, float scale)
{
    const int row  = blockIdx.x * 8 + (threadIdx.x >> 5);
    const int lane = threadIdx.x & 31;
    const int b    = row >> 10;
    const uint2*  r8 = (const uint2*)(Sh + (size_t)row * LSEQ) + lane;
    const float4* b4 = (const float4*)(s2 + (size_t)b * LSEQ) + lane;

    float4 v[4];
    #pragma unroll
    for (int i = 0; i < 4; i++) {
        uint2 u = r8[32 * i];
        float2 lo = __half22float2(*(__half2*)&u.x);
        float2 hi = __half22float2(*(__half2*)&u.y);
        float4 w = __ldg(b4 + 32 * i);
        v[i].x = (lo.x + w.x) * scale; v[i].y = (lo.y + w.y) * scale;
        v[i].z = (hi.x + w.z) * scale; v[i].w = (hi.y + w.w) * scale;
    }
    float mx = -3.4e38f;
    #pragma unroll
    for (int i = 0; i < 4; i++)
        mx = fmaxf(mx, fmaxf(fmaxf(v[i].x, v[i].y), fmaxf(v[i].z, v[i].w)));
    #pragma unroll
    for (int o = 16; o > 0; o >>= 1)
        mx = fmaxf(mx, __shfl_xor_sync(0xffffffffu, mx, o));
    float sum = 0.f;
    #pragma unroll
    for (int i = 0; i < 4; i++) {
        v[i].x = __expf(v[i].x - mx); v[i].y = __expf(v[i].y - mx);
        v[i].z = __expf(v[i].z - mx); v[i].w = __expf(v[i].w - mx);
        sum += v[i].x + v[i].y + v[i].z + v[i].w;
    }
    #pragma unroll
    for (int o = 16; o > 0; o >>= 1)
        sum += __shfl_xor_sync(0xffffffffu, sum, o);
    const float inv = 1.0f / sum;
    uint2* p8 = (uint2*)(P + (size_t)row * LSEQ) + lane;
    #pragma unroll
    for (int i = 0; i < 4; i++) {
        uint2 u;
        u.x = h2u(__floats2half2_rn(v[i].x * inv, v[i].y * inv));
        u.y = h2u(__floats2half2_rn(v[i].z * inv, v[i].w * inv));
        p8[32 * i] = u;
    }
}

extern "C" void kernel_launch(void* const* d_in, const int* in_sizes, int n_in,
                              void* d_out, int out_size)
{
    const float* q   = (const float*)d_in[0];
    const float* k   = (const float*)d_in[1];
    const float* v   = (const float*)d_in[2];
    const float* q_w = (const float*)d_in[3];
    const float* q_b = (const float*)d_in[4];
    const float* k_w = (const float*)d_in[5];
    const float* v_w = (const float*)d_in[7];
    const float* v_b = (const float*)d_in[8];
    float* out = (float*)d_out;

    __half *rq, *rk, *rv, *rwv, *rwqt, *rwkt, *gt2, *kg, *vpt, *sh, *p;
    float *gtp, *w2, *s2p;
    cudaGetSymbolAddress((void**)&rq,   g_rq);
    cudaGetSymbolAddress((void**)&rk,   g_rk);
    cudaGetSymbolAddress((void**)&rv,   g_rv);
    cudaGetSymbolAddress((void**)&rwv,  g_rwv);
    cudaGetSymbolAddress((void**)&rwqt, g_rwqt);
    cudaGetSymbolAddress((void**)&rwkt, g_rwkt);
    cudaGetSymbolAddress((void**)&gtp,  g_gtp);
    cudaGetSymbolAddress((void**)&gt2,  g_gt2);
    cudaGetSymbolAddress((void**)&w2,   g_w2);
    cudaGetSymbolAddress((void**)&s2p,  g_s2);
    cudaGetSymbolAddress((void**)&kg,   g_kg);
    cudaGetSymbolAddress((void**)&vpt,  g_vpt);
    cudaGetSymbolAddress((void**)&sh,   g_sh);
    cudaGetSymbolAddress((void**)&p,    g_p);

    static cudaStream_t s1 = nullptr, s2 = nullptr, s3 = nullptr;
    static cudaEvent_t eFork, eRk, eRq, eRv, eGt2, eS2, eVpt, eDone;
    if (!s1) {
        cudaStreamCreateWithFlags(&s1, cudaStreamNonBlocking);
        cudaStreamCreateWithFlags(&s2, cudaStreamNonBlocking);
        cudaStreamCreateWithFlags(&s3, cudaStreamNonBlocking);
        cudaEventCreateWithFlags(&eFork, cudaEventDisableTiming);
        cudaEventCreateWithFlags(&eRk,   cudaEventDisableTiming);
        cudaEventCreateWithFlags(&eRq,   cudaEventDisableTiming);
        cudaEventCreateWithFlags(&eRv,   cudaEventDisableTiming);
        cudaEventCreateWithFlags(&eGt2,  cudaEventDisableTiming);
        cudaEventCreateWithFlags(&eS2,   cudaEventDisableTiming);
        cudaEventCreateWithFlags(&eVpt,  cudaEventDisableTiming);
        cudaEventCreateWithFlags(&eDone, cudaEventDisableTiming);
        cudaFuncSetAttribute(hgemm_nt, cudaFuncAttributeMaxDynamicSharedMemorySize, SMEM_BYTES);
    }

    const int nq4 = BATCH * NQ * DIM / 4;
    const int nk4 = BATCH * LSEQ * DIM / 4;
    const int ng4 = DIM * DIM / 4;
    const float SCALE = 0.03608439182435161f;

    const size_t oRQ  = (size_t)HB * NQ * DIM;
    const size_t oRK  = (size_t)HB * LSEQ * DIM;
    const size_t oKG  = (size_t)HB * LSEQ * DIM;
    const size_t oS   = (size_t)HB * NQ * LSEQ;
    const size_t oS2  = (size_t)HB * LSEQ;
    const size_t oVPT = (size_t)HB * DIM * LSEQ;
    const size_t oOUT = (size_t)HB * NQ * DIM;

    // ---- fork ----
    cudaEventRecord(eFork, 0);
    cudaStreamWaitEvent(s1, eFork, 0);
    cudaStreamWaitEvent(s2, eFork, 0);
    cudaStreamWaitEvent(s3, eFork, 0);

    // s0: round k FIRST (gates kG), then kG/S chain lives here
    round3_h<<<nk4 / 256, 256, 0, 0>>>(k, rk, k, rk, k, rk, nk4, 0);
    cudaEventRecord(eRk, 0);

    // s1: weight transpose/round -> gt2 split-K (4 slices of K=192) -> reduce
    transpose_round<<<dim3(24, 24, 3), dim3(32, 8), 0, s1>>>(q_w, rwqt, k_w, rwkt, v_w, rwv);
    hgemm_nt<<<dim3(DIM / 128, DIM / 128, 4), 256, SMEM_BYTES, s1>>>(
        rwqt, rwkt, nullptr, gtp, 192, DIM, DIM, 192, 192, (long)DIM * DIM, 0, 0);
    reduce4_round<<<ng4 / 256, 256, 0, s1>>>(gtp, gt2, ng4);
    cudaEventRecord(eGt2, s1);

    // s2: w2 -> round v -> round q -> (after rk) s2
    compute_w2<<<DIM / 32, 256, 0, s2>>>(k_w, q_b, w2);
    round3_h<<<nk4 / 256, 256, 0, s2>>>(v, rv, v, rv, v, rv, nk4, 0);
    cudaEventRecord(eRv, s2);
    round3_h<<<nq4 / 256, 256, 0, s2>>>(q, rq, q, rq, q, rq, nq4, 0);
    cudaEventRecord(eRq, s2);
    cudaStreamWaitEvent(s2, eRk, 0);
    compute_s2<<<(BATCH * LSEQ) / 8, 256, 0, s2>>>(rk, w2, s2p);
    cudaEventRecord(eS2, s2);

    // s1: vpt (needs rv)  per-batch M=768, N=512
    cudaStreamWaitEvent(s1, eRv, 0);
    hgemm_nt<<<dim3(LSEQ / 128, DIM / 128, BATCH), 256, SMEM_BYTES, s1>>>(
        rwv, rv, v_b, vpt, DIM, DIM, LSEQ,
        0, (long)LSEQ * DIM, (long)DIM * LSEQ, 2, 1);
    cudaEventRecord(eVpt, s1);

    // ---- batch halves: s0 -> b 0..15, s3 -> b 16..31 ----

    // kG halves: M=8192, N=768 (need rk + gt2)
    cudaStreamWaitEvent(0, eGt2, 0);
    hgemm_nt<<<dim3(DIM / 128, (HB * LSEQ) / 128, 1), 256, SMEM_BYTES, 0>>>(
        rk, gt2, nullptr, kg, DIM, DIM, DIM, 0, 0, 0, 0, 1);
    cudaStreamWaitEvent(s3, eGt2, 0);
    cudaStreamWaitEvent(s3, eRk, 0);
    hgemm_nt<<<dim3(DIM / 128, (HB * LSEQ) / 128, 1), 256, SMEM_BYTES, s3>>>(
        rk + oRK, gt2, nullptr, kg + oKG, DIM, DIM, DIM, 0, 0, 0, 0, 1);

    // S halves: per-batch M=1024, N=512, K=768 -> fp16 scores (need rq)
    cudaStreamWaitEvent(0, eRq, 0);
    hgemm_nt<<<dim3(LSEQ / 128, NQ / 128, HB), 256, SMEM_BYTES, 0>>>(
        rq, kg, nullptr, sh, DIM, DIM, LSEQ,
        (long)NQ * DIM, (long)LSEQ * DIM, (long)NQ * LSEQ, 0, 1);
    cudaStreamWaitEvent(s3, eRq, 0);
    hgemm_nt<<<dim3(LSEQ / 128, NQ / 128, HB), 256, SMEM_BYTES, s3>>>(
        rq + oRQ, kg + oKG, nullptr, sh + oS, DIM, DIM, LSEQ,
        (long)NQ * DIM, (long)LSEQ * DIM, (long)NQ * LSEQ, 0, 1);

    // softmax halves (fp16 in) -> fp16 probs
    cudaStreamWaitEvent(0, eS2, 0);
    softmax_rows_h<<<(HB * NQ) / 8, 256, 0, 0>>>(sh, s2p, p, SCALE);
    cudaStreamWaitEvent(s3, eS2, 0);
    softmax_rows_h<<<(HB * NQ) / 8, 256, 0, s3>>>(sh + oS, s2p + oS2, p + oS, SCALE);

    // out halves: per-batch M=1024, N=768, K=512 -> fp32 to d_out
    cudaStreamWaitEvent(0, eVpt, 0);
    hgemm_nt<<<dim3(DIM / 128, NQ / 128, HB), 256, SMEM_BYTES, 0>>>(
        p, vpt, nullptr, out, LSEQ, LSEQ, DIM,
        (long)NQ * LSEQ, (long)DIM * LSEQ, (long)NQ * DIM, 0, 0);
    cudaStreamWaitEvent(s3, eVpt, 0);
    hgemm_nt<<<dim3(DIM / 128, NQ / 128, HB), 256, SMEM_BYTES, s3>>>(
        p + oS, vpt + oVPT, nullptr, out + oOUT, LSEQ, LSEQ, DIM,
        (long)NQ * LSEQ, (long)DIM * LSEQ, (long)NQ * DIM, 0, 0);

    // ---- join ----
    cudaEventRecord(eDone, s3);
    cudaStreamWaitEvent(0, eDone, 0);
}